// round 9
// baseline (speedup 1.0000x reference)
#include <cuda_runtime.h>
#include <cstdint>
#include <math.h>

// ---------------- problem constants ----------------
#define BB   8
#define LL   1024
#define CIN  32
#define DD   512
#define HH   8
#define DHD  64
#define DFF  2048
#define NLAYER 3
#define NCLS 16
#define UU   35
#define BL   (BB*LL)   // 8192

// ---------------- scratch (no allocations allowed) ----------------
__device__ float g_x  [BL*DD];
__device__ float g_q  [BL*DD];
__device__ float g_k  [BL*DD];
__device__ float g_v  [BL*DD];
__device__ float g_ao [BL*DD];     // attention output, ctx natural layout == reference reshape
__device__ float g_t1 [BL*DFF];    // FFN hidden
__device__ float g_t2 [BL*DD];     // generic D-wide temp
__device__ float g_pe [LL*DD];
__device__ int   g_idx[LL*UU];
__device__ float g_M  [BB*HH*LL];
__device__ int   g_top[BB*HH*UU];
__device__ float g_upd[BB*HH*UU*DHD];
__device__ float g_vmean[BB*HH*DHD];

// ---------------- threefry-2x32 (exact JAX) ----------------
__host__ __device__ inline void tf2x32(unsigned k0, unsigned k1,
                                       unsigned x0, unsigned x1,
                                       unsigned &o0, unsigned &o1) {
    unsigned ks2 = k0 ^ k1 ^ 0x1BD11BDAu;
    unsigned v0 = x0 + k0, v1 = x1 + k1;
#define TFR(r) { v0 += v1; v1 = (v1 << (r)) | (v1 >> (32 - (r))); v1 ^= v0; }
    TFR(13) TFR(15) TFR(26) TFR(6)   v0 += k1;  v1 += ks2 + 1u;
    TFR(17) TFR(29) TFR(16) TFR(24)  v0 += ks2; v1 += k0  + 2u;
    TFR(13) TFR(15) TFR(26) TFR(6)   v0 += k0;  v1 += k1  + 3u;
    TFR(17) TFR(29) TFR(16) TFR(24)  v0 += k1;  v1 += ks2 + 4u;
    TFR(13) TFR(15) TFR(26) TFR(6)   v0 += ks2; v1 += k0  + 5u;
#undef TFR
    o0 = v0; o1 = v1;
}

// PARTITIONABLE threefry random_bits (modern JAX default, jax>=0.4.30):
// per flat index j: counter = uint64 j -> (hi=0, lo=j);
// (o0,o1) = threefry(key, 0, j); bits32 = o0 ^ o1.
// idx = bits32 % 1024 (span pow2 -> randint multiplier term vanishes).
__global__ void idx_kernel(unsigned k0, unsigned k1) {
    const int TOT = LL * UU;   // 35840
    int j = blockIdx.x * blockDim.x + threadIdx.x;
    if (j >= TOT) return;
    unsigned o0, o1;
    tf2x32(k0, k1, 0u, (unsigned)j, o0, o1);
    g_idx[j] = (int)((o0 ^ o1) & 1023u);
}

// ---------------- positional encoding (double-precision transcendental core) ----------------
// Matches reference: earg = f32(2j) * f32(-ln(1e4)/512); div = exp(earg) (f32 result);
// arg = f32(l) * div (f32 multiply); pe = sin/cos(arg).
// Using double exp/sin/cos of the f32-rounded arguments keeps us within ~1 ulp of XLA
// and is immune to --use_fast_math's inaccurate __sinf at large args.
__global__ void pe_kernel() {
    int i = blockIdx.x * blockDim.x + threadIdx.x;
    if (i >= LL * DD) return;
    int l = i / DD, d = i - l * DD;
    float earg = (float)(2 * (d >> 1)) * (float)(-9.210340371976184 / 512.0);
    float div  = (float)exp((double)earg);
    float arg  = (float)l * div;                 // f32 multiply like reference
    double a   = (double)arg;
    g_pe[i] = (d & 1) ? (float)cos(a) : (float)sin(a);
}

// ---------------- circular conv1d (k=3) token embedding + PE ----------------
__global__ void embed_kernel(const float* __restrict__ xe, const float* __restrict__ cw) {
    int bl = blockIdx.x;           // 0..8191
    int tid = threadIdx.x;         // 128
    int b = bl >> 10, l = bl & 1023;
    __shared__ float sh[96];       // sh[c*3+t] = x_enc[b, (l-1+t) mod L, c]
    if (tid < 96) {
        int c = tid / 3, t = tid - c * 3;
        int li = (l - 1 + t + LL) & (LL - 1);
        sh[tid] = xe[((size_t)(b * LL + li)) * CIN + c];
    }
    __syncthreads();
#pragma unroll
    for (int j = 0; j < 4; j++) {
        int d = tid + j * 128;
        const float* w = cw + (size_t)d * 96;   // conv_w (D,C,3) row-major
        float acc = 0.f;
#pragma unroll
        for (int i = 0; i < 96; i++) acc = fmaf(sh[i], w[i], acc);
        g_x[(size_t)bl * DD + d] = acc + g_pe[l * DD + d];
    }
}

// ---------------- SGEMM: C[M,N] = A[M,K] * W[N,K]^T + bias (opt relu) ----------------
#define GBM 64
#define GBN 64
#define GBK 16
__global__ void __launch_bounds__(128)
gemm_nt_kernel(const float* __restrict__ A, const float* __restrict__ W,
               const float* __restrict__ bias, float* __restrict__ C,
               int M, int N, int K, int relu) {
    __shared__ float As[GBK][GBM + 4];
    __shared__ float Bs[GBK][GBN + 4];
    int tid = threadIdx.x;          // 128
    int bm = blockIdx.y * GBM;
    int bn = blockIdx.x * GBN;
    int tr = tid >> 3;              // 0..15 -> 4 rows each
    int tc = tid & 7;               // 0..7  -> 8 cols each
    float acc[4][8];
#pragma unroll
    for (int i = 0; i < 4; i++)
#pragma unroll
        for (int j = 0; j < 8; j++) acc[i][j] = 0.f;

    for (int k0 = 0; k0 < K; k0 += GBK) {
#pragma unroll
        for (int i = 0; i < 2; i++) {
            int li  = tid + i * 128;           // 0..255 -> 256 float4 per operand
            int row = li >> 2;
            int kq  = (li & 3) << 2;
            float4 va = *reinterpret_cast<const float4*>(A + (size_t)(bm + row) * K + k0 + kq);
            As[kq + 0][row] = va.x; As[kq + 1][row] = va.y;
            As[kq + 2][row] = va.z; As[kq + 3][row] = va.w;
            float4 vb = *reinterpret_cast<const float4*>(W + (size_t)(bn + row) * K + k0 + kq);
            Bs[kq + 0][row] = vb.x; Bs[kq + 1][row] = vb.y;
            Bs[kq + 2][row] = vb.z; Bs[kq + 3][row] = vb.w;
        }
        __syncthreads();
#pragma unroll
        for (int kk = 0; kk < GBK; kk++) {
            float a[4], b[8];
#pragma unroll
            for (int i = 0; i < 4; i++) a[i] = As[kk][tr * 4 + i];
#pragma unroll
            for (int j = 0; j < 8; j++) b[j] = Bs[kk][tc * 8 + j];
#pragma unroll
            for (int i = 0; i < 4; i++)
#pragma unroll
                for (int j = 0; j < 8; j++) acc[i][j] = fmaf(a[i], b[j], acc[i][j]);
        }
        __syncthreads();
    }
#pragma unroll
    for (int i = 0; i < 4; i++) {
        int row = bm + tr * 4 + i;
#pragma unroll
        for (int j = 0; j < 8; j++) {
            int col = bn + tc * 8 + j;
            float v = acc[i][j] + bias[col];
            if (relu) v = fmaxf(v, 0.f);
            C[(size_t)row * N + col] = v;
        }
    }
}

// ---------------- M scores: per (b,h,l): max_u(q.k_samp) - sum_u(q.k_samp)/L ----------------
__global__ void mscore_kernel() {
    int w = (blockIdx.x * blockDim.x + threadIdx.x) >> 5;   // warp id: (b*H+h)*L + l
    int lane = threadIdx.x & 31;
    int l = w & (LL - 1);
    int h = (w >> 10) & (HH - 1);
    int b = w >> 13;
    const float* qr = g_q + ((size_t)(b * LL + l) * DD + h * DHD);
    float q0 = qr[lane], q1 = qr[lane + 32];
    float mx = -3.4e38f, sm = 0.f;
    for (int u = 0; u < UU; u++) {
        int ki = g_idx[l * UU + u];
        const float* kr = g_k + ((size_t)(b * LL + ki) * DD + h * DHD);
        float s = q0 * kr[lane] + q1 * kr[lane + 32];
#pragma unroll
        for (int o = 16; o > 0; o >>= 1) s += __shfl_xor_sync(0xffffffffu, s, o);
        mx = fmaxf(mx, s);
        sm += s;
    }
    if (lane == 0) g_M[w] = mx - sm * (1.0f / 1024.0f);
}

// ---------------- top-35 per (b,h), tie -> lower index (matches lax.top_k) ----------------
__global__ void topk_kernel() {
    int bh = blockIdx.x, tid = threadIdx.x;   // 256
    __shared__ float sM[1024];
    __shared__ float rv[256];
    __shared__ int   ri[256];
    for (int i = tid; i < 1024; i += 256) sM[i] = g_M[bh * 1024 + i];
    __syncthreads();
    for (int u = 0; u < UU; u++) {
        float bv = -3.4e38f; int bi = 1 << 20;
#pragma unroll
        for (int j = 0; j < 4; j++) {
            int i = tid * 4 + j;
            float v = sM[i];
            if (v > bv || (v == bv && i < bi)) { bv = v; bi = i; }
        }
        rv[tid] = bv; ri[tid] = bi; __syncthreads();
        for (int st = 128; st > 0; st >>= 1) {
            if (tid < st) {
                float v2 = rv[tid + st]; int i2 = ri[tid + st];
                if (v2 > rv[tid] || (v2 == rv[tid] && i2 < ri[tid])) { rv[tid] = v2; ri[tid] = i2; }
            }
            __syncthreads();
        }
        if (tid == 0) { g_top[bh * UU + u] = ri[0]; sM[ri[0]] = -3.4e38f; }
        __syncthreads();
    }
}

// ---------------- v mean over L per (b,h,e) ----------------
__global__ void vmean_kernel() {
    int bh = blockIdx.x, e = threadIdx.x;    // 64 threads
    int h = bh & 7, b = bh >> 3;
    float s = 0.f;
    for (int l = 0; l < LL; l++) s += g_v[((size_t)(b * LL + l) * DD) + h * DHD + e];
    g_vmean[bh * DHD + e] = s * (1.0f / 1024.0f);
}

// ---------------- full attention for selected queries ----------------
__global__ void __launch_bounds__(256) attn_kernel() {
    int blk = blockIdx.x;                    // (b*H+h)*U + u
    int u = blk % UU, bh = blk / UU;
    int h = bh & 7, b = bh >> 3;
    int tid = threadIdx.x;                   // 256
    __shared__ float qs[64];
    __shared__ float sc[1024];
    __shared__ float red[256];
    int trow = g_top[bh * UU + u];
    if (tid < 64) qs[tid] = g_q[((size_t)(b * LL + trow) * DD) + h * DHD + tid];
    __syncthreads();
    float lmax = -3.4e38f;
#pragma unroll
    for (int j = 0; j < 4; j++) {
        int k = tid + j * 256;
        const float* kr = g_k + ((size_t)(b * LL + k) * DD + h * DHD);
        float s = 0.f;
#pragma unroll
        for (int e = 0; e < 64; e++) s = fmaf(qs[e], kr[e], s);
        s *= 0.125f;                         // 1/sqrt(64)
        sc[k] = s;
        lmax = fmaxf(lmax, s);
    }
    red[tid] = lmax; __syncthreads();
    for (int st = 128; st > 0; st >>= 1) { if (tid < st) red[tid] = fmaxf(red[tid], red[tid + st]); __syncthreads(); }
    float bmax = red[0]; __syncthreads();
    float lsum = 0.f;
#pragma unroll
    for (int j = 0; j < 4; j++) { int k = tid + j * 256; float e = expf(sc[k] - bmax); sc[k] = e; lsum += e; }
    red[tid] = lsum; __syncthreads();
    for (int st = 128; st > 0; st >>= 1) { if (tid < st) red[tid] += red[tid + st]; __syncthreads(); }
    float inv = 1.0f / red[0]; __syncthreads();
    int e = tid & 63, cs = tid >> 6;
    float p = 0.f;
    for (int k = cs * 256; k < cs * 256 + 256; k++)
        p = fmaf(sc[k], g_v[((size_t)(b * LL + k) * DD) + h * DHD + e], p);
    red[tid] = p; __syncthreads();
    if (tid < 64) {
        float r = (red[tid] + red[tid + 64] + red[tid + 128] + red[tid + 192]) * inv;
        g_upd[((size_t)(bh * UU + u)) * DHD + tid] = r;
    }
}

// ---------------- ctx assembly (natural (B,H,L,dh) layout == reference's reshape) ----------------
__global__ void ctxfill_kernel() {
    int i = blockIdx.x * blockDim.x + threadIdx.x;
    if (i >= BL * DD) return;
    int e = i & 63;
    int h = (i >> 16) & 7;
    int b = i >> 19;
    g_ao[i] = g_vmean[(b * HH + h) * DHD + e];
}
__global__ void scatter_kernel() {
    int blk = blockIdx.x;                   // (b*H+h)*U + u
    int e = threadIdx.x;                    // 64
    int u = blk % UU, bh = blk / UU;
    int trow = g_top[bh * UU + u];
    g_ao[((size_t)(bh * LL + trow)) * 64 + e] = g_upd[(size_t)blk * 64 + e];
}

// ---------------- layernorm (in-place on g_x, optional residual add) ----------------
__global__ void ln_kernel(const float* __restrict__ add,
                          const float* __restrict__ gam, const float* __restrict__ bet) {
    int r = blockIdx.x, tid = threadIdx.x;  // 256 threads, 2 elems each
    __shared__ float red[256];
    size_t base = (size_t)r * DD;
    float x0 = g_x[base + tid], x1 = g_x[base + tid + 256];
    if (add) { x0 += add[base + tid]; x1 += add[base + tid + 256]; }
    red[tid] = x0 + x1; __syncthreads();
    for (int st = 128; st > 0; st >>= 1) { if (tid < st) red[tid] += red[tid + st]; __syncthreads(); }
    float m = red[0] * (1.0f / 512.0f); __syncthreads();
    float d0 = x0 - m, d1 = x1 - m;
    red[tid] = d0 * d0 + d1 * d1; __syncthreads();
    for (int st = 128; st > 0; st >>= 1) { if (tid < st) red[tid] += red[tid + st]; __syncthreads(); }
    float inv = 1.0f / sqrtf(red[0] * (1.0f / 512.0f) + 1e-5f);
    g_x[base + tid]       = d0 * inv * gam[tid]       + bet[tid];
    g_x[base + tid + 256] = d1 * inv * gam[tid + 256] + bet[tid + 256];
}

// ---------------- final: out[b,c] = sum_i x[b,i]*mark[b,i/512]*fc_w[c,i] + fc_b[c] ----------------
__global__ void final_kernel(const float* __restrict__ mark, const float* __restrict__ fcw,
                             const float* __restrict__ fcb, float* __restrict__ out) {
    int b = blockIdx.x >> 4, c = blockIdx.x & 15;
    int tid = threadIdx.x;                  // 256
    __shared__ float red[256];
    const float* xr = g_x + (size_t)b * LL * DD;
    const float* wr = fcw + (size_t)c * LL * DD;
    const float* mk = mark + b * LL;
    float s = 0.f;
    for (int i = tid; i < LL * DD; i += 256)
        s = fmaf(xr[i] * mk[i >> 9], wr[i], s);
    red[tid] = s; __syncthreads();
    for (int st = 128; st > 0; st >>= 1) { if (tid < st) red[tid] += red[tid + st]; __syncthreads(); }
    if (tid == 0) out[b * NCLS + c] = red[0] + fcb[c];
}

// ---------------- host ----------------
extern "C" void kernel_launch(void* const* d_in, const int* in_sizes, int n_in,
                              void* d_out, int out_size) {
    (void)in_sizes; (void)n_in; (void)out_size;
    const float* x_enc  = (const float*)d_in[0];
    const float* x_mark = (const float*)d_in[1];
    const float* conv_w = (const float*)d_in[2];
    const float* Wq = (const float*)d_in[3];
    const float* bq = (const float*)d_in[4];
    const float* Wk = (const float*)d_in[5];
    const float* bk = (const float*)d_in[6];
    const float* Wv = (const float*)d_in[7];
    const float* bv = (const float*)d_in[8];
    const float* Wo = (const float*)d_in[9];
    const float* bo = (const float*)d_in[10];
    const float* W1 = (const float*)d_in[11];
    const float* b1 = (const float*)d_in[12];
    const float* W2 = (const float*)d_in[13];
    const float* b2 = (const float*)d_in[14];
    const float* g1 = (const float*)d_in[15];
    const float* be1= (const float*)d_in[16];
    const float* g2 = (const float*)d_in[17];
    const float* be2= (const float*)d_in[18];
    const float* gF = (const float*)d_in[19];
    const float* bF = (const float*)d_in[20];
    const float* fcw= (const float*)d_in[21];
    const float* fcb= (const float*)d_in[22];
    float* out = (float*)d_out;

    float *px, *pq, *pk, *pv, *pao, *pt1, *pt2;
    cudaGetSymbolAddress((void**)&px,  g_x);
    cudaGetSymbolAddress((void**)&pq,  g_q);
    cudaGetSymbolAddress((void**)&pk,  g_k);
    cudaGetSymbolAddress((void**)&pv,  g_v);
    cudaGetSymbolAddress((void**)&pao, g_ao);
    cudaGetSymbolAddress((void**)&pt1, g_t1);
    cudaGetSymbolAddress((void**)&pt2, g_t2);

    pe_kernel<<<(LL * DD + 255) / 256, 256>>>();
    embed_kernel<<<BL, 128>>>(x_enc, conv_w);

    for (int l = 0; l < NLAYER; l++) {
        // layer key = fold_in(key(42), l) = threefry2x32((0,42), (0,l))  [foldlike, version-independent]
        unsigned lk0, lk1;
        tf2x32(0u, 42u, 0u, (unsigned)l, lk0, lk1);
        // randint: k1,k2 = split(layer_key). Modern JAX (threefry_partitionable=True) split is
        // "foldlike": child i = threefry(key, hi(i), lo(i)). Second child (i=1):
        unsigned c0, c1;
        tf2x32(lk0, lk1, 0u, 1u, c0, c1);
        // lower_bits[j] = o0 ^ o1 of threefry(k2, 0, j)  (partitionable random_bits, 32-bit)

        gemm_nt_kernel<<<dim3(DD / GBN, BL / GBM), 128>>>(px, Wq + (size_t)l * DD * DD, bq + l * DD, pq, BL, DD, DD, 0);
        gemm_nt_kernel<<<dim3(DD / GBN, BL / GBM), 128>>>(px, Wk + (size_t)l * DD * DD, bk + l * DD, pk, BL, DD, DD, 0);
        gemm_nt_kernel<<<dim3(DD / GBN, BL / GBM), 128>>>(px, Wv + (size_t)l * DD * DD, bv + l * DD, pv, BL, DD, DD, 0);

        idx_kernel<<<(LL * UU + 255) / 256, 256>>>(c0, c1);
        mscore_kernel<<<(BB * HH * LL) / 8, 256>>>();
        topk_kernel<<<BB * HH, 256>>>();
        vmean_kernel<<<BB * HH, 64>>>();
        attn_kernel<<<BB * HH * UU, 256>>>();
        ctxfill_kernel<<<(BL * DD + 255) / 256, 256>>>();
        scatter_kernel<<<BB * HH * UU, 64>>>();

        gemm_nt_kernel<<<dim3(DD / GBN, BL / GBM), 128>>>(pao, Wo + (size_t)l * DD * DD, bo + l * DD, pt2, BL, DD, DD, 0);
        ln_kernel<<<BL, 256>>>(pt2, g1 + l * DD, be1 + l * DD);

        gemm_nt_kernel<<<dim3(DFF / GBN, BL / GBM), 128>>>(px, W1 + (size_t)l * DFF * DD, b1 + l * DFF, pt1, BL, DFF, DD, 1);
        gemm_nt_kernel<<<dim3(DD / GBN, BL / GBM), 128>>>(pt1, W2 + (size_t)l * DD * DFF, b2 + l * DD, pt2, BL, DD, DFF, 0);
        ln_kernel<<<BL, 256>>>(pt2, g2 + l * DD, be2 + l * DD);
    }

    ln_kernel<<<BL, 256>>>(nullptr, gF, bF);
    final_kernel<<<BB * NCLS, 256>>>(x_mark, fcw, fcb, out);
}

// round 10
// speedup vs baseline: 1.4933x; 1.4933x over previous
#include <cuda_runtime.h>
#include <cstdint>
#include <math.h>

// ---------------- problem constants ----------------
#define BB   8
#define LL   1024
#define CIN  32
#define DD   512
#define HH   8
#define DHD  64
#define DFF  2048
#define NLAYER 3
#define NCLS 16
#define UU   35
#define BL   (BB*LL)   // 8192

// ---------------- scratch (no allocations allowed) ----------------
__device__ float g_x  [BL*DD];
__device__ float g_q  [BL*DD];
__device__ float g_k  [BL*DD];
__device__ float g_v  [BL*DD];
__device__ float g_ao [BL*DD];
__device__ float g_t1 [BL*DFF];
__device__ float g_t2 [BL*DD];
__device__ float g_pe [LL*DD];
__device__ int   g_idx[LL*UU];
__device__ float g_M  [BB*HH*LL];
__device__ int   g_top[BB*HH*UU];
__device__ float g_upd[BB*HH*UU*DHD];
__device__ float g_vmean[BB*HH*DHD];

// ---------------- packed f32x2 helpers ----------------
__device__ __forceinline__ unsigned long long pack2(float lo, float hi) {
    float2 t = make_float2(lo, hi);
    return *reinterpret_cast<unsigned long long*>(&t);
}
__device__ __forceinline__ float2 unpack2(unsigned long long v) {
    return *reinterpret_cast<float2*>(&v);
}
#define FMA2(acc, a, b) asm("fma.rn.f32x2 %0, %1, %2, %0;" : "+l"(acc) : "l"(a), "l"(b))

// ---------------- threefry-2x32 (exact JAX) ----------------
__host__ __device__ inline void tf2x32(unsigned k0, unsigned k1,
                                       unsigned x0, unsigned x1,
                                       unsigned &o0, unsigned &o1) {
    unsigned ks2 = k0 ^ k1 ^ 0x1BD11BDAu;
    unsigned v0 = x0 + k0, v1 = x1 + k1;
#define TFR(r) { v0 += v1; v1 = (v1 << (r)) | (v1 >> (32 - (r))); v1 ^= v0; }
    TFR(13) TFR(15) TFR(26) TFR(6)   v0 += k1;  v1 += ks2 + 1u;
    TFR(17) TFR(29) TFR(16) TFR(24)  v0 += ks2; v1 += k0  + 2u;
    TFR(13) TFR(15) TFR(26) TFR(6)   v0 += k0;  v1 += k1  + 3u;
    TFR(17) TFR(29) TFR(16) TFR(24)  v0 += k1;  v1 += ks2 + 4u;
    TFR(13) TFR(15) TFR(26) TFR(6)   v0 += ks2; v1 += k0  + 5u;
#undef TFR
    o0 = v0; o1 = v1;
}

// PARTITIONABLE threefry random_bits: bits[j] = o0^o1 of tf(key, 0, j); idx = bits & 1023.
__global__ void idx_kernel(unsigned k0, unsigned k1) {
    const int TOT = LL * UU;
    int j = blockIdx.x * blockDim.x + threadIdx.x;
    if (j >= TOT) return;
    unsigned o0, o1;
    tf2x32(k0, k1, 0u, (unsigned)j, o0, o1);
    g_idx[j] = (int)((o0 ^ o1) & 1023u);
}

// ---------------- positional encoding ----------------
__global__ void pe_kernel() {
    int i = blockIdx.x * blockDim.x + threadIdx.x;
    if (i >= LL * DD) return;
    int l = i / DD, d = i - l * DD;
    float earg = (float)(2 * (d >> 1)) * (float)(-9.210340371976184 / 512.0);
    float div  = (float)exp((double)earg);
    float arg  = (float)l * div;
    double a   = (double)arg;
    g_pe[i] = (d & 1) ? (float)cos(a) : (float)sin(a);
}

// ---------------- circular conv1d (k=3) embed + PE; 16 tokens per block ----------------
__global__ void __launch_bounds__(128) embed_kernel(const float* __restrict__ xe, const float* __restrict__ cw) {
    int blk = blockIdx.x;                 // 0..511 : (b, l-chunk)
    int tid = threadIdx.x;                // 128
    int b = blk >> 6;                     // 512 / 64 chunks per batch
    int l0 = (blk & 63) << 4;             // chunk start
    __shared__ float xs[18][32];          // rows l0-1 .. l0+16 (circular), 32 channels
    for (int i = tid; i < 18 * 32; i += 128) {
        int r = i >> 5, c = i & 31;
        int gl = (l0 - 1 + r + LL) & (LL - 1);
        xs[r][c] = xe[((size_t)(b * LL + gl)) * CIN + c];
    }
    __syncthreads();
#pragma unroll
    for (int j = 0; j < 4; j++) {
        int d = tid + j * 128;
        const float* w = cw + (size_t)d * 96;   // conv_w (D,C,3)
        float acc[16];
#pragma unroll
        for (int li = 0; li < 16; li++) acc[li] = 0.f;
        for (int c = 0; c < CIN; c++) {
#pragma unroll
            for (int t = 0; t < 3; t++) {
                float wv = w[c * 3 + t];
#pragma unroll
                for (int li = 0; li < 16; li++)
                    acc[li] = fmaf(xs[li + t][c], wv, acc[li]);
            }
        }
#pragma unroll
        for (int li = 0; li < 16; li++) {
            int l = l0 + li;
            g_x[(size_t)(b * LL + l) * DD + d] = acc[li] + g_pe[l * DD + d];
        }
    }
}

// ---------------- SGEMM 128x128x8, 8x8/thread, f32x2 packed FMA ----------------
#define BM 128
#define BN 128
#define BKK 8
__global__ void __launch_bounds__(256, 2)
gemm_nt_kernel(const float* __restrict__ A, const float* __restrict__ W,
               const float* __restrict__ bias, float* __restrict__ C,
               int M, int N, int K, int relu) {
    __shared__ __align__(16) float As[BKK][BM + 4];
    __shared__ __align__(16) float Bs[BKK][BN + 4];
    int tid = threadIdx.x;           // 256
    int bm = blockIdx.y * BM;
    int bn = blockIdx.x * BN;
    int tr = tid >> 4;               // 0..15 -> rows tr*8..tr*8+7
    int tc = tid & 15;               // 0..15 -> cols tc*8..tc*8+7
    int lrow = tid >> 1;             // 0..127
    int lcol = (tid & 1) << 2;       // 0 or 4

    const float* Ap = A + (size_t)(bm + lrow) * K + lcol;
    const float* Wp = W + (size_t)(bn + lrow) * K + lcol;

    unsigned long long acc[8][4];
#pragma unroll
    for (int i = 0; i < 8; i++)
#pragma unroll
        for (int p = 0; p < 4; p++) acc[i][p] = 0ull;

    float4 va = *reinterpret_cast<const float4*>(Ap);
    float4 vb = *reinterpret_cast<const float4*>(Wp);

    for (int k0 = 0; k0 < K; k0 += BKK) {
        As[lcol + 0][lrow] = va.x; As[lcol + 1][lrow] = va.y;
        As[lcol + 2][lrow] = va.z; As[lcol + 3][lrow] = va.w;
        Bs[lcol + 0][lrow] = vb.x; Bs[lcol + 1][lrow] = vb.y;
        Bs[lcol + 2][lrow] = vb.z; Bs[lcol + 3][lrow] = vb.w;
        __syncthreads();
        if (k0 + BKK < K) {
            va = *reinterpret_cast<const float4*>(Ap + k0 + BKK);
            vb = *reinterpret_cast<const float4*>(Wp + k0 + BKK);
        }
#pragma unroll
        for (int kk = 0; kk < BKK; kk++) {
            float4 a0 = *reinterpret_cast<const float4*>(&As[kk][tr * 8]);
            float4 a1 = *reinterpret_cast<const float4*>(&As[kk][tr * 8 + 4]);
            float4 b0 = *reinterpret_cast<const float4*>(&Bs[kk][tc * 8]);
            float4 b1 = *reinterpret_cast<const float4*>(&Bs[kk][tc * 8 + 4]);
            unsigned long long bbp[4];
            bbp[0] = pack2(b0.x, b0.y); bbp[1] = pack2(b0.z, b0.w);
            bbp[2] = pack2(b1.x, b1.y); bbp[3] = pack2(b1.z, b1.w);
            float av[8] = {a0.x, a0.y, a0.z, a0.w, a1.x, a1.y, a1.z, a1.w};
#pragma unroll
            for (int i = 0; i < 8; i++) {
                unsigned long long aa = pack2(av[i], av[i]);
#pragma unroll
                for (int p = 0; p < 4; p++)
                    FMA2(acc[i][p], aa, bbp[p]);
            }
        }
        __syncthreads();
    }

    int cb = bn + tc * 8;
    float4 bia0 = *reinterpret_cast<const float4*>(bias + cb);
    float4 bia1 = *reinterpret_cast<const float4*>(bias + cb + 4);
#pragma unroll
    for (int i = 0; i < 8; i++) {
        int row = bm + tr * 8 + i;
        float2 f0 = unpack2(acc[i][0]), f1 = unpack2(acc[i][1]);
        float2 f2 = unpack2(acc[i][2]), f3 = unpack2(acc[i][3]);
        float4 o0 = make_float4(f0.x + bia0.x, f0.y + bia0.y, f1.x + bia0.z, f1.y + bia0.w);
        float4 o1 = make_float4(f2.x + bia1.x, f2.y + bia1.y, f3.x + bia1.z, f3.y + bia1.w);
        if (relu) {
            o0.x = fmaxf(o0.x, 0.f); o0.y = fmaxf(o0.y, 0.f); o0.z = fmaxf(o0.z, 0.f); o0.w = fmaxf(o0.w, 0.f);
            o1.x = fmaxf(o1.x, 0.f); o1.y = fmaxf(o1.y, 0.f); o1.z = fmaxf(o1.z, 0.f); o1.w = fmaxf(o1.w, 0.f);
        }
        *reinterpret_cast<float4*>(C + (size_t)row * N + cb)     = o0;
        *reinterpret_cast<float4*>(C + (size_t)row * N + cb + 4) = o1;
    }
}

// ---------------- M scores ----------------
__global__ void mscore_kernel() {
    int w = (blockIdx.x * blockDim.x + threadIdx.x) >> 5;
    int lane = threadIdx.x & 31;
    int l = w & (LL - 1);
    int h = (w >> 10) & (HH - 1);
    int b = w >> 13;
    const float* qr = g_q + ((size_t)(b * LL + l) * DD + h * DHD);
    float q0 = qr[lane], q1 = qr[lane + 32];
    float mx = -3.4e38f, sm = 0.f;
    for (int u = 0; u < UU; u++) {
        int ki = g_idx[l * UU + u];
        const float* kr = g_k + ((size_t)(b * LL + ki) * DD + h * DHD);
        float s = q0 * kr[lane] + q1 * kr[lane + 32];
#pragma unroll
        for (int o = 16; o > 0; o >>= 1) s += __shfl_xor_sync(0xffffffffu, s, o);
        mx = fmaxf(mx, s);
        sm += s;
    }
    if (lane == 0) g_M[w] = mx - sm * (1.0f / 1024.0f);
}

// ---------------- top-35 per (b,h) ----------------
__global__ void topk_kernel() {
    int bh = blockIdx.x, tid = threadIdx.x;   // 256
    __shared__ float sM[1024];
    __shared__ float rv[256];
    __shared__ int   ri[256];
    for (int i = tid; i < 1024; i += 256) sM[i] = g_M[bh * 1024 + i];
    __syncthreads();
    for (int u = 0; u < UU; u++) {
        float bv = -3.4e38f; int bi = 1 << 20;
#pragma unroll
        for (int j = 0; j < 4; j++) {
            int i = tid * 4 + j;
            float v = sM[i];
            if (v > bv || (v == bv && i < bi)) { bv = v; bi = i; }
        }
        rv[tid] = bv; ri[tid] = bi; __syncthreads();
        for (int st = 128; st > 0; st >>= 1) {
            if (tid < st) {
                float v2 = rv[tid + st]; int i2 = ri[tid + st];
                if (v2 > rv[tid] || (v2 == rv[tid] && i2 < ri[tid])) { rv[tid] = v2; ri[tid] = i2; }
            }
            __syncthreads();
        }
        if (tid == 0) { g_top[bh * UU + u] = ri[0]; sM[ri[0]] = -3.4e38f; }
        __syncthreads();
    }
}

// ---------------- v mean over L per (b,h,e), 4-way split ----------------
__global__ void vmean_kernel() {
    int bh = blockIdx.x;
    int tid = threadIdx.x;              // 256
    int e = tid & 63, qq = tid >> 6;
    int h = bh & 7, b = bh >> 3;
    __shared__ float red[256];
    const float* base = g_v + (size_t)b * LL * DD + h * DHD + e;
    float s = 0.f;
    for (int l = qq * 256; l < qq * 256 + 256; l++)
        s += base[(size_t)l * DD];
    red[tid] = s; __syncthreads();
    if (qq == 0)
        g_vmean[bh * DHD + e] = (red[e] + red[e + 64] + red[e + 128] + red[e + 192]) * (1.0f / 1024.0f);
}

// ---------------- full attention for selected queries ----------------
__global__ void __launch_bounds__(256) attn_kernel() {
    int blk = blockIdx.x;                    // (b*H+h)*U + u
    int u = blk % UU, bh = blk / UU;
    int h = bh & 7, b = bh >> 3;
    int tid = threadIdx.x;                   // 256
    __shared__ float qs[64];
    __shared__ float sc[1024];
    __shared__ float red[256];
    int trow = g_top[bh * UU + u];
    if (tid < 64) qs[tid] = g_q[((size_t)(b * LL + trow) * DD) + h * DHD + tid];
    __syncthreads();
    float lmax = -3.4e38f;
#pragma unroll
    for (int j = 0; j < 4; j++) {
        int k = tid + j * 256;
        const float* kr = g_k + ((size_t)(b * LL + k) * DD + h * DHD);
        float s = 0.f;
#pragma unroll
        for (int e = 0; e < 64; e++) s = fmaf(qs[e], kr[e], s);
        s *= 0.125f;
        sc[k] = s;
        lmax = fmaxf(lmax, s);
    }
    red[tid] = lmax; __syncthreads();
    for (int st = 128; st > 0; st >>= 1) { if (tid < st) red[tid] = fmaxf(red[tid], red[tid + st]); __syncthreads(); }
    float bmax = red[0]; __syncthreads();
    float lsum = 0.f;
#pragma unroll
    for (int j = 0; j < 4; j++) { int k = tid + j * 256; float e = expf(sc[k] - bmax); sc[k] = e; lsum += e; }
    red[tid] = lsum; __syncthreads();
    for (int st = 128; st > 0; st >>= 1) { if (tid < st) red[tid] += red[tid + st]; __syncthreads(); }
    float inv = 1.0f / red[0]; __syncthreads();
    int e = tid & 63, cs = tid >> 6;
    float p = 0.f;
    for (int k = cs * 256; k < cs * 256 + 256; k++)
        p = fmaf(sc[k], g_v[((size_t)(b * LL + k) * DD) + h * DHD + e], p);
    red[tid] = p; __syncthreads();
    if (tid < 64) {
        float r = (red[tid] + red[tid + 64] + red[tid + 128] + red[tid + 192]) * inv;
        g_upd[((size_t)(bh * UU + u)) * DHD + tid] = r;
    }
}

// ---------------- ctx assembly ----------------
__global__ void ctxfill_kernel() {
    int i = blockIdx.x * blockDim.x + threadIdx.x;
    if (i >= BL * DD) return;
    int e = i & 63;
    int h = (i >> 16) & 7;
    int b = i >> 19;
    g_ao[i] = g_vmean[(b * HH + h) * DHD + e];
}
__global__ void scatter_kernel() {
    int blk = blockIdx.x;
    int e = threadIdx.x;                    // 64
    int u = blk % UU, bh = blk / UU;
    int trow = g_top[bh * UU + u];
    g_ao[((size_t)(bh * LL + trow)) * 64 + e] = g_upd[(size_t)blk * 64 + e];
}

// ---------------- layernorm ----------------
__global__ void ln_kernel(const float* __restrict__ add,
                          const float* __restrict__ gam, const float* __restrict__ bet) {
    int r = blockIdx.x, tid = threadIdx.x;
    __shared__ float red[256];
    size_t base = (size_t)r * DD;
    float x0 = g_x[base + tid], x1 = g_x[base + tid + 256];
    if (add) { x0 += add[base + tid]; x1 += add[base + tid + 256]; }
    red[tid] = x0 + x1; __syncthreads();
    for (int st = 128; st > 0; st >>= 1) { if (tid < st) red[tid] += red[tid + st]; __syncthreads(); }
    float m = red[0] * (1.0f / 512.0f); __syncthreads();
    float d0 = x0 - m, d1 = x1 - m;
    red[tid] = d0 * d0 + d1 * d1; __syncthreads();
    for (int st = 128; st > 0; st >>= 1) { if (tid < st) red[tid] += red[tid + st]; __syncthreads(); }
    float inv = 1.0f / sqrtf(red[0] * (1.0f / 512.0f) + 1e-5f);
    g_x[base + tid]       = d0 * inv * gam[tid]       + bet[tid];
    g_x[base + tid + 256] = d1 * inv * gam[tid + 256] + bet[tid + 256];
}

// ---------------- final fc ----------------
__global__ void final_kernel(const float* __restrict__ mark, const float* __restrict__ fcw,
                             const float* __restrict__ fcb, float* __restrict__ out) {
    int b = blockIdx.x >> 4, c = blockIdx.x & 15;
    int tid = threadIdx.x;
    __shared__ float red[256];
    const float* xr = g_x + (size_t)b * LL * DD;
    const float* wr = fcw + (size_t)c * LL * DD;
    const float* mk = mark + b * LL;
    float s = 0.f;
    for (int i = tid; i < LL * DD; i += 256)
        s = fmaf(xr[i] * mk[i >> 9], wr[i], s);
    red[tid] = s; __syncthreads();
    for (int st = 128; st > 0; st >>= 1) { if (tid < st) red[tid] += red[tid + st]; __syncthreads(); }
    if (tid == 0) out[b * NCLS + c] = red[0] + fcb[c];
}

// ---------------- host ----------------
extern "C" void kernel_launch(void* const* d_in, const int* in_sizes, int n_in,
                              void* d_out, int out_size) {
    (void)in_sizes; (void)n_in; (void)out_size;
    const float* x_enc  = (const float*)d_in[0];
    const float* x_mark = (const float*)d_in[1];
    const float* conv_w = (const float*)d_in[2];
    const float* Wq = (const float*)d_in[3];
    const float* bq = (const float*)d_in[4];
    const float* Wk = (const float*)d_in[5];
    const float* bk = (const float*)d_in[6];
    const float* Wv = (const float*)d_in[7];
    const float* bv = (const float*)d_in[8];
    const float* Wo = (const float*)d_in[9];
    const float* bo = (const float*)d_in[10];
    const float* W1 = (const float*)d_in[11];
    const float* b1 = (const float*)d_in[12];
    const float* W2 = (const float*)d_in[13];
    const float* b2 = (const float*)d_in[14];
    const float* g1 = (const float*)d_in[15];
    const float* be1= (const float*)d_in[16];
    const float* g2 = (const float*)d_in[17];
    const float* be2= (const float*)d_in[18];
    const float* gF = (const float*)d_in[19];
    const float* bF = (const float*)d_in[20];
    const float* fcw= (const float*)d_in[21];
    const float* fcb= (const float*)d_in[22];
    float* out = (float*)d_out;

    float *px, *pq, *pk, *pv, *pao, *pt1, *pt2;
    cudaGetSymbolAddress((void**)&px,  g_x);
    cudaGetSymbolAddress((void**)&pq,  g_q);
    cudaGetSymbolAddress((void**)&pk,  g_k);
    cudaGetSymbolAddress((void**)&pv,  g_v);
    cudaGetSymbolAddress((void**)&pao, g_ao);
    cudaGetSymbolAddress((void**)&pt1, g_t1);
    cudaGetSymbolAddress((void**)&pt2, g_t2);

    pe_kernel<<<(LL * DD + 255) / 256, 256>>>();
    embed_kernel<<<BL / 16, 128>>>(x_enc, conv_w);

    for (int l = 0; l < NLAYER; l++) {
        unsigned lk0, lk1;
        tf2x32(0u, 42u, 0u, (unsigned)l, lk0, lk1);
        unsigned c0, c1;
        tf2x32(lk0, lk1, 0u, 1u, c0, c1);   // second child of split(layer_key)

        gemm_nt_kernel<<<dim3(DD / BN, BL / BM), 256>>>(px, Wq + (size_t)l * DD * DD, bq + l * DD, pq, BL, DD, DD, 0);
        gemm_nt_kernel<<<dim3(DD / BN, BL / BM), 256>>>(px, Wk + (size_t)l * DD * DD, bk + l * DD, pk, BL, DD, DD, 0);
        gemm_nt_kernel<<<dim3(DD / BN, BL / BM), 256>>>(px, Wv + (size_t)l * DD * DD, bv + l * DD, pv, BL, DD, DD, 0);

        idx_kernel<<<(LL * UU + 255) / 256, 256>>>(c0, c1);
        mscore_kernel<<<(BB * HH * LL) / 8, 256>>>();
        topk_kernel<<<BB * HH, 256>>>();
        vmean_kernel<<<BB * HH, 256>>>();
        attn_kernel<<<BB * HH * UU, 256>>>();
        ctxfill_kernel<<<(BL * DD + 255) / 256, 256>>>();
        scatter_kernel<<<BB * HH * UU, 64>>>();

        gemm_nt_kernel<<<dim3(DD / BN, BL / BM), 256>>>(pao, Wo + (size_t)l * DD * DD, bo + l * DD, pt2, BL, DD, DD, 0);
        ln_kernel<<<BL, 256>>>(pt2, g1 + l * DD, be1 + l * DD);

        gemm_nt_kernel<<<dim3(DFF / BN, BL / BM), 256>>>(px, W1 + (size_t)l * DFF * DD, b1 + l * DFF, pt1, BL, DFF, DD, 1);
        gemm_nt_kernel<<<dim3(DD / BN, BL / BM), 256>>>(pt1, W2 + (size_t)l * DD * DFF, b2 + l * DD, pt2, BL, DD, DFF, 0);
        ln_kernel<<<BL, 256>>>(pt2, g2 + l * DD, be2 + l * DD);
    }

    ln_kernel<<<BL, 256>>>(nullptr, gF, bF);
    final_kernel<<<BB * NCLS, 256>>>(x_mark, fcw, fcb, out);
}

// round 11
// speedup vs baseline: 1.9750x; 1.3225x over previous
#include <cuda_runtime.h>
#include <cstdint>
#include <math.h>

// ---------------- problem constants ----------------
#define BB   8
#define LL   1024
#define CIN  32
#define DD   512
#define HH   8
#define DHD  64
#define DFF  2048
#define NLAYER 3
#define NCLS 16
#define UU   35
#define BL   (BB*LL)   // 8192

// ---------------- scratch (no allocations allowed) ----------------
__device__ float g_x  [BL*DD];
__device__ float g_q  [BL*DD];
__device__ float g_k  [BL*DD];
__device__ float g_v  [BL*DD];
__device__ float g_ao [BL*DD];
__device__ float g_t1 [BL*DFF];
__device__ float g_t2 [BL*DD];
__device__ float g_pe [LL*DD];
__device__ int   g_idx[LL*UU];
__device__ float g_M  [BB*HH*LL];
__device__ int   g_top[BB*HH*UU];
__device__ float g_upd[BB*HH*UU*DHD];
__device__ float g_vmean[BB*HH*DHD];

// ---------------- packed f32x2 helpers ----------------
typedef unsigned long long ull;
__device__ __forceinline__ ull pack2(float lo, float hi) {
    float2 t = make_float2(lo, hi);
    return *reinterpret_cast<ull*>(&t);
}
__device__ __forceinline__ float2 unpack2(ull v) {
    return *reinterpret_cast<float2*>(&v);
}
#define FMA2(acc, a, b) asm("fma.rn.f32x2 %0, %1, %2, %0;" : "+l"(acc) : "l"(a), "l"(b))

// ---------------- threefry-2x32 (exact JAX) ----------------
__host__ __device__ inline void tf2x32(unsigned k0, unsigned k1,
                                       unsigned x0, unsigned x1,
                                       unsigned &o0, unsigned &o1) {
    unsigned ks2 = k0 ^ k1 ^ 0x1BD11BDAu;
    unsigned v0 = x0 + k0, v1 = x1 + k1;
#define TFR(r) { v0 += v1; v1 = (v1 << (r)) | (v1 >> (32 - (r))); v1 ^= v0; }
    TFR(13) TFR(15) TFR(26) TFR(6)   v0 += k1;  v1 += ks2 + 1u;
    TFR(17) TFR(29) TFR(16) TFR(24)  v0 += ks2; v1 += k0  + 2u;
    TFR(13) TFR(15) TFR(26) TFR(6)   v0 += k0;  v1 += k1  + 3u;
    TFR(17) TFR(29) TFR(16) TFR(24)  v0 += k1;  v1 += ks2 + 4u;
    TFR(13) TFR(15) TFR(26) TFR(6)   v0 += ks2; v1 += k0  + 5u;
#undef TFR
    o0 = v0; o1 = v1;
}

// PARTITIONABLE threefry random_bits: bits[j] = o0^o1 of tf(key, 0, j); idx = bits & 1023.
__global__ void idx_kernel(unsigned k0, unsigned k1) {
    const int TOT = LL * UU;
    int j = blockIdx.x * blockDim.x + threadIdx.x;
    if (j >= TOT) return;
    unsigned o0, o1;
    tf2x32(k0, k1, 0u, (unsigned)j, o0, o1);
    g_idx[j] = (int)((o0 ^ o1) & 1023u);
}

// ---------------- positional encoding ----------------
__global__ void pe_kernel() {
    int i = blockIdx.x * blockDim.x + threadIdx.x;
    if (i >= LL * DD) return;
    int l = i / DD, d = i - l * DD;
    float earg = (float)(2 * (d >> 1)) * (float)(-9.210340371976184 / 512.0);
    float div  = (float)exp((double)earg);
    float arg  = (float)l * div;
    double a   = (double)arg;
    g_pe[i] = (d & 1) ? (float)cos(a) : (float)sin(a);
}

// ---------------- circular conv1d (k=3) embed + PE; 16 tokens per block ----------------
__global__ void __launch_bounds__(128) embed_kernel(const float* __restrict__ xe, const float* __restrict__ cw) {
    int blk = blockIdx.x;
    int tid = threadIdx.x;
    int b = blk >> 6;
    int l0 = (blk & 63) << 4;
    __shared__ float xs[18][32];
    for (int i = tid; i < 18 * 32; i += 128) {
        int r = i >> 5, c = i & 31;
        int gl = (l0 - 1 + r + LL) & (LL - 1);
        xs[r][c] = xe[((size_t)(b * LL + gl)) * CIN + c];
    }
    __syncthreads();
#pragma unroll
    for (int j = 0; j < 4; j++) {
        int d = tid + j * 128;
        const float* w = cw + (size_t)d * 96;
        float acc[16];
#pragma unroll
        for (int li = 0; li < 16; li++) acc[li] = 0.f;
        for (int c = 0; c < CIN; c++) {
#pragma unroll
            for (int t = 0; t < 3; t++) {
                float wv = w[c * 3 + t];
#pragma unroll
                for (int li = 0; li < 16; li++)
                    acc[li] = fmaf(xs[li + t][c], wv, acc[li]);
            }
        }
#pragma unroll
        for (int li = 0; li < 16; li++) {
            int l = l0 + li;
            g_x[(size_t)(b * LL + l) * DD + d] = acc[li] + g_pe[l * DD + d];
        }
    }
}

// ---------------- SGEMM 128x128x16, double-buffered, bank-swizzled, f32x2 ----------------
#define BM 128
#define BN 128
#define BK2 16
#define SP 132           // smem row pitch (floats): 16B-aligned, STS 2-way tolerated
__device__ __forceinline__ int swz(int c) { return c ^ ((c & 32) >> 3); }

__global__ void __launch_bounds__(256, 2)
gemm_nt_kernel(const float* __restrict__ A, const float* __restrict__ W,
               const float* __restrict__ bias, float* __restrict__ C,
               int M, int N, int K, int relu) {
    __shared__ __align__(16) float As[2][BK2][SP];
    __shared__ __align__(16) float Bs[2][BK2][SP];
    int tid = threadIdx.x;           // 256
    int bm = blockIdx.y * BM;
    int bn = blockIdx.x * BN;
    int tr = tid >> 4;               // 0..15 -> rows tr*8..+7
    int tc = tid & 15;               // 0..15 -> cols tc*8..+7
    int lr = tid >> 2;               // 0..63
    int lc = (tid & 3) << 2;         // 0,4,8,12

    int swlr0 = swz(lr);
    int swlr1 = swz(lr + 64);
    int sa0 = swz(tr * 8), sa1 = swz(tr * 8 + 4);
    int sb0 = swz(tc * 8), sb1 = swz(tc * 8 + 4);

    const float* Ar0 = A + (size_t)(bm + lr) * K + lc;
    const float* Ar1 = Ar0 + (size_t)64 * K;
    const float* Wr0 = W + (size_t)(bn + lr) * K + lc;
    const float* Wr1 = Wr0 + (size_t)64 * K;

    ull acc[8][4];
#pragma unroll
    for (int i = 0; i < 8; i++)
#pragma unroll
        for (int p = 0; p < 4; p++) acc[i][p] = 0ull;

    float4 na0 = *reinterpret_cast<const float4*>(Ar0);
    float4 na1 = *reinterpret_cast<const float4*>(Ar1);
    float4 nb0 = *reinterpret_cast<const float4*>(Wr0);
    float4 nb1 = *reinterpret_cast<const float4*>(Wr1);

#define STORE_STAGE(buf) do { \
    As[buf][lc + 0][swlr0] = na0.x; As[buf][lc + 1][swlr0] = na0.y; \
    As[buf][lc + 2][swlr0] = na0.z; As[buf][lc + 3][swlr0] = na0.w; \
    As[buf][lc + 0][swlr1] = na1.x; As[buf][lc + 1][swlr1] = na1.y; \
    As[buf][lc + 2][swlr1] = na1.z; As[buf][lc + 3][swlr1] = na1.w; \
    Bs[buf][lc + 0][swlr0] = nb0.x; Bs[buf][lc + 1][swlr0] = nb0.y; \
    Bs[buf][lc + 2][swlr0] = nb0.z; Bs[buf][lc + 3][swlr0] = nb0.w; \
    Bs[buf][lc + 0][swlr1] = nb1.x; Bs[buf][lc + 1][swlr1] = nb1.y; \
    Bs[buf][lc + 2][swlr1] = nb1.z; Bs[buf][lc + 3][swlr1] = nb1.w; \
} while (0)

    STORE_STAGE(0);
    __syncthreads();

    int nst = K / BK2;
    for (int ks = 0; ks < nst; ks++) {
        int cur = ks & 1;
        if (ks + 1 < nst) {
            int off = (ks + 1) * BK2;
            na0 = *reinterpret_cast<const float4*>(Ar0 + off);
            na1 = *reinterpret_cast<const float4*>(Ar1 + off);
            nb0 = *reinterpret_cast<const float4*>(Wr0 + off);
            nb1 = *reinterpret_cast<const float4*>(Wr1 + off);
        }
#pragma unroll
        for (int kk = 0; kk < BK2; kk++) {
            float4 a0 = *reinterpret_cast<const float4*>(&As[cur][kk][sa0]);
            float4 a1 = *reinterpret_cast<const float4*>(&As[cur][kk][sa1]);
            float4 b0 = *reinterpret_cast<const float4*>(&Bs[cur][kk][sb0]);
            float4 b1 = *reinterpret_cast<const float4*>(&Bs[cur][kk][sb1]);
            const ull* bp0 = reinterpret_cast<const ull*>(&b0);
            const ull* bp1 = reinterpret_cast<const ull*>(&b1);
            ull bbp[4] = { bp0[0], bp0[1], bp1[0], bp1[1] };
            float av[8] = {a0.x, a0.y, a0.z, a0.w, a1.x, a1.y, a1.z, a1.w};
#pragma unroll
            for (int i = 0; i < 8; i++) {
                ull aa = pack2(av[i], av[i]);
#pragma unroll
                for (int p = 0; p < 4; p++)
                    FMA2(acc[i][p], aa, bbp[p]);
            }
        }
        if (ks + 1 < nst) STORE_STAGE(cur ^ 1);
        __syncthreads();
    }
#undef STORE_STAGE

    int cb = bn + tc * 8;
    float4 bia0 = *reinterpret_cast<const float4*>(bias + cb);
    float4 bia1 = *reinterpret_cast<const float4*>(bias + cb + 4);
#pragma unroll
    for (int i = 0; i < 8; i++) {
        int row = bm + tr * 8 + i;
        float2 f0 = unpack2(acc[i][0]), f1 = unpack2(acc[i][1]);
        float2 f2 = unpack2(acc[i][2]), f3 = unpack2(acc[i][3]);
        float4 o0 = make_float4(f0.x + bia0.x, f0.y + bia0.y, f1.x + bia0.z, f1.y + bia0.w);
        float4 o1 = make_float4(f2.x + bia1.x, f2.y + bia1.y, f3.x + bia1.z, f3.y + bia1.w);
        if (relu) {
            o0.x = fmaxf(o0.x, 0.f); o0.y = fmaxf(o0.y, 0.f); o0.z = fmaxf(o0.z, 0.f); o0.w = fmaxf(o0.w, 0.f);
            o1.x = fmaxf(o1.x, 0.f); o1.y = fmaxf(o1.y, 0.f); o1.z = fmaxf(o1.z, 0.f); o1.w = fmaxf(o1.w, 0.f);
        }
        *reinterpret_cast<float4*>(C + (size_t)row * N + cb)     = o0;
        *reinterpret_cast<float4*>(C + (size_t)row * N + cb + 4) = o1;
    }
}

// ---------------- M scores ----------------
__global__ void mscore_kernel() {
    int w = (blockIdx.x * blockDim.x + threadIdx.x) >> 5;
    int lane = threadIdx.x & 31;
    int l = w & (LL - 1);
    int h = (w >> 10) & (HH - 1);
    int b = w >> 13;
    const float* qr = g_q + ((size_t)(b * LL + l) * DD + h * DHD);
    float q0 = qr[lane], q1 = qr[lane + 32];
    float mx = -3.4e38f, sm = 0.f;
    for (int u = 0; u < UU; u++) {
        int ki = g_idx[l * UU + u];
        const float* kr = g_k + ((size_t)(b * LL + ki) * DD + h * DHD);
        float s = q0 * kr[lane] + q1 * kr[lane + 32];
#pragma unroll
        for (int o = 16; o > 0; o >>= 1) s += __shfl_xor_sync(0xffffffffu, s, o);
        mx = fmaxf(mx, s);
        sm += s;
    }
    if (lane == 0) g_M[w] = mx - sm * (1.0f / 1024.0f);
}

// ---------------- top-35 per (b,h) ----------------
__global__ void topk_kernel() {
    int bh = blockIdx.x, tid = threadIdx.x;   // 256
    __shared__ float sM[1024];
    __shared__ float rv[256];
    __shared__ int   ri[256];
    for (int i = tid; i < 1024; i += 256) sM[i] = g_M[bh * 1024 + i];
    __syncthreads();
    for (int u = 0; u < UU; u++) {
        float bv = -3.4e38f; int bi = 1 << 20;
#pragma unroll
        for (int j = 0; j < 4; j++) {
            int i = tid * 4 + j;
            float v = sM[i];
            if (v > bv || (v == bv && i < bi)) { bv = v; bi = i; }
        }
        rv[tid] = bv; ri[tid] = bi; __syncthreads();
        for (int st = 128; st > 0; st >>= 1) {
            if (tid < st) {
                float v2 = rv[tid + st]; int i2 = ri[tid + st];
                if (v2 > rv[tid] || (v2 == rv[tid] && i2 < ri[tid])) { rv[tid] = v2; ri[tid] = i2; }
            }
            __syncthreads();
        }
        if (tid == 0) { g_top[bh * UU + u] = ri[0]; sM[ri[0]] = -3.4e38f; }
        __syncthreads();
    }
}

// ---------------- v mean over L per (b,h,e), 4-way split ----------------
__global__ void vmean_kernel() {
    int bh = blockIdx.x;
    int tid = threadIdx.x;              // 256
    int e = tid & 63, qq = tid >> 6;
    int h = bh & 7, b = bh >> 3;
    __shared__ float red[256];
    const float* base = g_v + (size_t)b * LL * DD + h * DHD + e;
    float s = 0.f;
    for (int l = qq * 256; l < qq * 256 + 256; l++)
        s += base[(size_t)l * DD];
    red[tid] = s; __syncthreads();
    if (qq == 0)
        g_vmean[bh * DHD + e] = (red[e] + red[e + 64] + red[e + 128] + red[e + 192]) * (1.0f / 1024.0f);
}

// ---------------- full attention for selected queries ----------------
__global__ void __launch_bounds__(256) attn_kernel() {
    int blk = blockIdx.x;                    // (b*H+h)*U + u
    int u = blk % UU, bh = blk / UU;
    int h = bh & 7, b = bh >> 3;
    int tid = threadIdx.x;                   // 256
    __shared__ float qs[64];
    __shared__ float sc[1024];
    __shared__ float red[256];
    int trow = g_top[bh * UU + u];
    if (tid < 64) qs[tid] = g_q[((size_t)(b * LL + trow) * DD) + h * DHD + tid];
    __syncthreads();
    float lmax = -3.4e38f;
#pragma unroll
    for (int j = 0; j < 4; j++) {
        int k = tid + j * 256;
        const float4* kr4 = reinterpret_cast<const float4*>(g_k + ((size_t)(b * LL + k) * DD + h * DHD));
        float s = 0.f;
#pragma unroll
        for (int e4 = 0; e4 < 16; e4++) {
            float4 kv = kr4[e4];
            s = fmaf(qs[e4 * 4 + 0], kv.x, s);
            s = fmaf(qs[e4 * 4 + 1], kv.y, s);
            s = fmaf(qs[e4 * 4 + 2], kv.z, s);
            s = fmaf(qs[e4 * 4 + 3], kv.w, s);
        }
        s *= 0.125f;
        sc[k] = s;
        lmax = fmaxf(lmax, s);
    }
    red[tid] = lmax; __syncthreads();
    for (int st = 128; st > 0; st >>= 1) { if (tid < st) red[tid] = fmaxf(red[tid], red[tid + st]); __syncthreads(); }
    float bmax = red[0]; __syncthreads();
    float lsum = 0.f;
#pragma unroll
    for (int j = 0; j < 4; j++) { int k = tid + j * 256; float e = expf(sc[k] - bmax); sc[k] = e; lsum += e; }
    red[tid] = lsum; __syncthreads();
    for (int st = 128; st > 0; st >>= 1) { if (tid < st) red[tid] += red[tid + st]; __syncthreads(); }
    float inv = 1.0f / red[0]; __syncthreads();
    int e = tid & 63, cs = tid >> 6;
    float p = 0.f;
    for (int k = cs * 256; k < cs * 256 + 256; k++)
        p = fmaf(sc[k], g_v[((size_t)(b * LL + k) * DD) + h * DHD + e], p);
    red[tid] = p; __syncthreads();
    if (tid < 64) {
        float r = (red[tid] + red[tid + 64] + red[tid + 128] + red[tid + 192]) * inv;
        g_upd[((size_t)(bh * UU + u)) * DHD + tid] = r;
    }
}

// ---------------- ctx assembly ----------------
__global__ void ctxfill_kernel() {
    int i = blockIdx.x * blockDim.x + threadIdx.x;
    if (i >= BL * DD) return;
    int e = i & 63;
    int h = (i >> 16) & 7;
    int b = i >> 19;
    g_ao[i] = g_vmean[(b * HH + h) * DHD + e];
}
__global__ void scatter_kernel() {
    int blk = blockIdx.x;
    int e = threadIdx.x;                    // 64
    int u = blk % UU, bh = blk / UU;
    int trow = g_top[bh * UU + u];
    g_ao[((size_t)(bh * LL + trow)) * 64 + e] = g_upd[(size_t)blk * 64 + e];
}

// ---------------- layernorm ----------------
__global__ void ln_kernel(const float* __restrict__ add,
                          const float* __restrict__ gam, const float* __restrict__ bet) {
    int r = blockIdx.x, tid = threadIdx.x;
    __shared__ float red[256];
    size_t base = (size_t)r * DD;
    float x0 = g_x[base + tid], x1 = g_x[base + tid + 256];
    if (add) { x0 += add[base + tid]; x1 += add[base + tid + 256]; }
    red[tid] = x0 + x1; __syncthreads();
    for (int st = 128; st > 0; st >>= 1) { if (tid < st) red[tid] += red[tid + st]; __syncthreads(); }
    float m = red[0] * (1.0f / 512.0f); __syncthreads();
    float d0 = x0 - m, d1 = x1 - m;
    red[tid] = d0 * d0 + d1 * d1; __syncthreads();
    for (int st = 128; st > 0; st >>= 1) { if (tid < st) red[tid] += red[tid + st]; __syncthreads(); }
    float inv = 1.0f / sqrtf(red[0] * (1.0f / 512.0f) + 1e-5f);
    g_x[base + tid]       = d0 * inv * gam[tid]       + bet[tid];
    g_x[base + tid + 256] = d1 * inv * gam[tid + 256] + bet[tid + 256];
}

// ---------------- final fc ----------------
__global__ void final_kernel(const float* __restrict__ mark, const float* __restrict__ fcw,
                             const float* __restrict__ fcb, float* __restrict__ out) {
    int b = blockIdx.x >> 4, c = blockIdx.x & 15;
    int tid = threadIdx.x;
    __shared__ float red[256];
    const float* xr = g_x + (size_t)b * LL * DD;
    const float* wr = fcw + (size_t)c * LL * DD;
    const float* mk = mark + b * LL;
    float s = 0.f;
    for (int i = tid; i < LL * DD; i += 256)
        s = fmaf(xr[i] * mk[i >> 9], wr[i], s);
    red[tid] = s; __syncthreads();
    for (int st = 128; st > 0; st >>= 1) { if (tid < st) red[tid] += red[tid + st]; __syncthreads(); }
    if (tid == 0) out[b * NCLS + c] = red[0] + fcb[c];
}

// ---------------- host ----------------
extern "C" void kernel_launch(void* const* d_in, const int* in_sizes, int n_in,
                              void* d_out, int out_size) {
    (void)in_sizes; (void)n_in; (void)out_size;
    const float* x_enc  = (const float*)d_in[0];
    const float* x_mark = (const float*)d_in[1];
    const float* conv_w = (const float*)d_in[2];
    const float* Wq = (const float*)d_in[3];
    const float* bq = (const float*)d_in[4];
    const float* Wk = (const float*)d_in[5];
    const float* bk = (const float*)d_in[6];
    const float* Wv = (const float*)d_in[7];
    const float* bv = (const float*)d_in[8];
    const float* Wo = (const float*)d_in[9];
    const float* bo = (const float*)d_in[10];
    const float* W1 = (const float*)d_in[11];
    const float* b1 = (const float*)d_in[12];
    const float* W2 = (const float*)d_in[13];
    const float* b2 = (const float*)d_in[14];
    const float* g1 = (const float*)d_in[15];
    const float* be1= (const float*)d_in[16];
    const float* g2 = (const float*)d_in[17];
    const float* be2= (const float*)d_in[18];
    const float* gF = (const float*)d_in[19];
    const float* bF = (const float*)d_in[20];
    const float* fcw= (const float*)d_in[21];
    const float* fcb= (const float*)d_in[22];
    float* out = (float*)d_out;

    float *px, *pq, *pk, *pv, *pao, *pt1, *pt2;
    cudaGetSymbolAddress((void**)&px,  g_x);
    cudaGetSymbolAddress((void**)&pq,  g_q);
    cudaGetSymbolAddress((void**)&pk,  g_k);
    cudaGetSymbolAddress((void**)&pv,  g_v);
    cudaGetSymbolAddress((void**)&pao, g_ao);
    cudaGetSymbolAddress((void**)&pt1, g_t1);
    cudaGetSymbolAddress((void**)&pt2, g_t2);

    pe_kernel<<<(LL * DD + 255) / 256, 256>>>();
    embed_kernel<<<BL / 16, 128>>>(x_enc, conv_w);

    for (int l = 0; l < NLAYER; l++) {
        unsigned lk0, lk1;
        tf2x32(0u, 42u, 0u, (unsigned)l, lk0, lk1);
        unsigned c0, c1;
        tf2x32(lk0, lk1, 0u, 1u, c0, c1);   // second child of split(layer_key)

        gemm_nt_kernel<<<dim3(DD / BN, BL / BM), 256>>>(px, Wq + (size_t)l * DD * DD, bq + l * DD, pq, BL, DD, DD, 0);
        gemm_nt_kernel<<<dim3(DD / BN, BL / BM), 256>>>(px, Wk + (size_t)l * DD * DD, bk + l * DD, pk, BL, DD, DD, 0);
        gemm_nt_kernel<<<dim3(DD / BN, BL / BM), 256>>>(px, Wv + (size_t)l * DD * DD, bv + l * DD, pv, BL, DD, DD, 0);

        idx_kernel<<<(LL * UU + 255) / 256, 256>>>(c0, c1);
        mscore_kernel<<<(BB * HH * LL) / 8, 256>>>();
        topk_kernel<<<BB * HH, 256>>>();
        vmean_kernel<<<BB * HH, 256>>>();
        attn_kernel<<<BB * HH * UU, 256>>>();
        ctxfill_kernel<<<(BL * DD + 255) / 256, 256>>>();
        scatter_kernel<<<BB * HH * UU, 64>>>();

        gemm_nt_kernel<<<dim3(DD / BN, BL / BM), 256>>>(pao, Wo + (size_t)l * DD * DD, bo + l * DD, pt2, BL, DD, DD, 0);
        ln_kernel<<<BL, 256>>>(pt2, g1 + l * DD, be1 + l * DD);

        gemm_nt_kernel<<<dim3(DFF / BN, BL / BM), 256>>>(px, W1 + (size_t)l * DFF * DD, b1 + l * DFF, pt1, BL, DFF, DD, 1);
        gemm_nt_kernel<<<dim3(DD / BN, BL / BM), 256>>>(pt1, W2 + (size_t)l * DD * DFF, b2 + l * DD, pt2, BL, DD, DFF, 0);
        ln_kernel<<<BL, 256>>>(pt2, g2 + l * DD, be2 + l * DD);
    }

    ln_kernel<<<BL, 256>>>(nullptr, gF, bF);
    final_kernel<<<BB * NCLS, 256>>>(x_mark, fcw, fcb, out);
}